// round 11
// baseline (speedup 1.0000x reference)
#include <cuda_runtime.h>

#define NN   100000
#define EE   3200000
#define IND  128
#define OUTD 64

// Scratch (device globals — no allocation allowed)
__device__ float g_h[NN * OUTD];      // 25.6 MB
__device__ float g_hs[NN];
__device__ float g_ht[NN];
__device__ int   g_deg[NN];
__device__ int   g_cur[NN];           // running cursor, pre-seeded = g_off
__device__ int   g_off[NN + 1];
__device__ int2  g_sp[EE];            // {src, bitcast(p)} permuted by target
__device__ int   g_is64;              // 1 if edge_index is int64, 0 if int32

// ---------------------------------------------------------------------------
// Detect edge_index dtype: int64 values < 2^31 have zero odd 32-bit words.
// 128 random int32 node-ids in [0,100000) being all zero is impossible.
// ---------------------------------------------------------------------------
__global__ void detect_kernel(const int* __restrict__ ei_raw) {
    if (threadIdx.x == 0 && blockIdx.x == 0) {
        int all0 = 1;
        for (int k = 0; k < 128; ++k)
            if (ei_raw[2 * k + 1] != 0) { all0 = 0; break; }
        g_is64 = all0;
    }
}

// Decode index and clamp into [0, NN): if the dtype detection is ever wrong
// this degrades a hardware trap into a measurable wrong answer (diagnostic),
// and costs two IMNMX hidden under the index LDG latency.
__device__ __forceinline__ int load_idx(const void* ei, int is64, long long pos) {
    int v = is64 ? (int)((const long long*)ei)[pos] : ((const int*)ei)[pos];
    return min(max(v, 0), NN - 1);
}

// ---------------------------------------------------------------------------
// Zero the degree histogram
// ---------------------------------------------------------------------------
__global__ void zero_kernel() {
    int i = blockIdx.x * blockDim.x + threadIdx.x;
    if (i < NN) g_deg[i] = 0;
}

// ---------------------------------------------------------------------------
// h = x @ W   (100000x128 @ 128x64), smem-tiled
// ---------------------------------------------------------------------------
__global__ __launch_bounds__(256) void gemm_kernel(const float* __restrict__ x,
                                                   const float* __restrict__ W) {
    __shared__ float Ws[IND * OUTD];   // 32 KB
    __shared__ float xs[16 * IND];     // 8 KB

    for (int i = threadIdx.x; i < IND * OUTD; i += 256) Ws[i] = W[i];

    const int c  = threadIdx.x & 63;
    const int rg = threadIdx.x >> 6;          // 0..3
    const int rowBase = blockIdx.x * 64;

    for (int it = 0; it < 4; ++it) {
        const int r0 = rowBase + it * 16;
        __syncthreads();
        for (int i = threadIdx.x; i < 16 * IND / 4; i += 256) {
            int rr = r0 + (i * 4) / IND;
            float4 v = make_float4(0.f, 0.f, 0.f, 0.f);
            if (rr < NN)
                v = reinterpret_cast<const float4*>(x)[(size_t)r0 * (IND / 4) + i];
            reinterpret_cast<float4*>(xs)[i] = v;
        }
        __syncthreads();

        float acc0 = 0.f, acc1 = 0.f, acc2 = 0.f, acc3 = 0.f;
        const float* xr = xs + rg * 4 * IND;
        #pragma unroll 16
        for (int k = 0; k < IND; ++k) {
            float wv = Ws[k * OUTD + c];
            acc0 += xr[0 * IND + k] * wv;
            acc1 += xr[1 * IND + k] * wv;
            acc2 += xr[2 * IND + k] * wv;
            acc3 += xr[3 * IND + k] * wv;
        }
        const int row = r0 + rg * 4;
        if (row + 0 < NN) g_h[(row + 0) * OUTD + c] = acc0;
        if (row + 1 < NN) g_h[(row + 1) * OUTD + c] = acc1;
        if (row + 2 < NN) g_h[(row + 2) * OUTD + c] = acc2;
        if (row + 3 < NN) g_h[(row + 3) * OUTD + c] = acc3;
    }
}

// ---------------------------------------------------------------------------
// hs = h @ a_src, ht = h @ a_tgt  — one warp per node row
// ---------------------------------------------------------------------------
__global__ __launch_bounds__(256) void attn_vec_kernel(const float* __restrict__ a_src,
                                                       const float* __restrict__ a_tgt) {
    int warp = (blockIdx.x * blockDim.x + threadIdx.x) >> 5;
    int lane = threadIdx.x & 31;
    if (warp >= NN) return;
    float h0 = g_h[warp * OUTD + lane];
    float h1 = g_h[warp * OUTD + 32 + lane];
    float ps = h0 * __ldg(a_src + lane) + h1 * __ldg(a_src + 32 + lane);
    float pt = h0 * __ldg(a_tgt + lane) + h1 * __ldg(a_tgt + 32 + lane);
    #pragma unroll
    for (int o = 16; o; o >>= 1) {
        ps += __shfl_xor_sync(0xFFFFFFFFu, ps, o);
        pt += __shfl_xor_sync(0xFFFFFFFFu, pt, o);
    }
    if (lane == 0) { g_hs[warp] = ps; g_ht[warp] = pt; }
}

// ---------------------------------------------------------------------------
// Degree histogram over targets
// ---------------------------------------------------------------------------
__global__ __launch_bounds__(256) void hist_kernel(const void* __restrict__ ei) {
    int e = blockIdx.x * blockDim.x + threadIdx.x;
    if (e >= EE) return;
    const int is64 = g_is64;
    int t = load_idx(ei, is64, (long long)EE + e);
    atomicAdd(&g_deg[t], 1);
}

// ---------------------------------------------------------------------------
// Exclusive scan of g_deg -> g_off, also seeding g_cur = g_off
// (single block, 1024 threads, chunked)
// ---------------------------------------------------------------------------
__global__ __launch_bounds__(1024) void scan_kernel() {
    __shared__ int partial[1024];
    const int CH  = (NN + 1023) / 1024;        // 98
    const int tid = threadIdx.x;
    const int begin = tid * CH;
    const int end   = min(begin + CH, NN);

    int sum = 0;
    for (int i = begin; i < end; ++i) sum += g_deg[i];
    partial[tid] = sum;
    __syncthreads();

    // Hillis-Steele inclusive scan over partial[]
    for (int off = 1; off < 1024; off <<= 1) {
        int v = (tid >= off) ? partial[tid - off] : 0;
        __syncthreads();
        partial[tid] += v;
        __syncthreads();
    }

    int run = (tid == 0) ? 0 : partial[tid - 1];
    for (int i = begin; i < end; ++i) {
        g_off[i] = run;
        g_cur[i] = run;                        // seed cursor with base offset
        run += g_deg[i];
    }
    if (tid == 1023) g_off[NN] = run;          // == EE
}

// ---------------------------------------------------------------------------
// Permute edges into target-sorted buckets: g_sp[pos] = {src, p}
// p = exp(leaky_relu(hs[s]+ht[t]) * w)   (shift-free softmax numerator)
// Single atomic returns the absolute position (cursor pre-seeded with g_off).
// ---------------------------------------------------------------------------
__global__ __launch_bounds__(256) void permute_kernel(const void* __restrict__ ei,
                                                      const float* __restrict__ w) {
    int e = blockIdx.x * blockDim.x + threadIdx.x;
    if (e >= EE) return;
    const int is64 = g_is64;
    int s = load_idx(ei, is64, e);
    int t = load_idx(ei, is64, (long long)EE + e);
    float v = g_hs[s] + g_ht[t];
    v = v > 0.f ? v : 0.2f * v;
    v *= __ldg(w + e);
    float p = __expf(v);
    int pos = atomicAdd(&g_cur[t], 1);
    g_sp[pos] = make_int2(s, __float_as_int(p));
}

// ---------------------------------------------------------------------------
// Gather: one warp per target node, SINGLE fused pass.
//   out[t] = inv * sum_e p_e * h[src_e],  inv = 1/(sum_e p_e + 1e-10)
// Edge descriptors read once per 32 edges (coalesced, one int2/lane), then
// broadcast via shfl; h-row gathers are the only inner-loop L2 traffic.
// ---------------------------------------------------------------------------
__global__ __launch_bounds__(256) void gather_kernel(float* __restrict__ out) {
    int t    = (blockIdx.x * blockDim.x + threadIdx.x) >> 5;
    int lane = threadIdx.x & 31;
    if (t >= NN) return;

    const int base = g_off[t];
    const int end  = g_off[t + 1];

    float psum = 0.f, a0 = 0.f, a1 = 0.f;

    int cbase = base;
    for (; cbase + 32 <= end; cbase += 32) {
        int2 my = __ldg(&g_sp[cbase + lane]);
        psum += __int_as_float(my.y);
        #pragma unroll 4
        for (int k = 0; k < 32; ++k) {
            int   src = __shfl_sync(0xFFFFFFFFu, my.x, k);
            float p   = __int_as_float(__shfl_sync(0xFFFFFFFFu, my.y, k));
            const float* hr = g_h + (size_t)src * OUTD;
            a0 += p * hr[lane];
            a1 += p * hr[32 + lane];
        }
    }
    if (cbase < end) {
        const int n = end - cbase;
        int2 my = make_int2(0, 0);
        if (cbase + lane < end) my = __ldg(&g_sp[cbase + lane]);
        psum += __int_as_float(my.y);
        for (int k = 0; k < n; ++k) {
            int   src = __shfl_sync(0xFFFFFFFFu, my.x, k);
            float p   = __int_as_float(__shfl_sync(0xFFFFFFFFu, my.y, k));
            const float* hr = g_h + (size_t)src * OUTD;
            a0 += p * hr[lane];
            a1 += p * hr[32 + lane];
        }
    }

    #pragma unroll
    for (int o = 16; o; o >>= 1)
        psum += __shfl_xor_sync(0xFFFFFFFFu, psum, o);
    const float inv = 1.0f / (psum + 1e-10f);

    out[(size_t)t * OUTD + lane]      = a0 * inv;
    out[(size_t)t * OUTD + 32 + lane] = a1 * inv;
}

// ---------------------------------------------------------------------------
extern "C" void kernel_launch(void* const* d_in, const int* in_sizes, int n_in,
                              void* d_out, int out_size) {
    const float* x      = (const float*)d_in[0];
    const void*  ei     = d_in[1];
    const float* ew     = (const float*)d_in[2];
    const float* W      = (const float*)d_in[3];
    const float* a_src  = (const float*)d_in[4];
    const float* a_tgt  = (const float*)d_in[5];
    float*       out    = (float*)d_out;

    detect_kernel<<<1, 32>>>((const int*)ei);
    zero_kernel<<<(NN + 255) / 256, 256>>>();
    gemm_kernel<<<(NN + 63) / 64, 256>>>(x, W);
    attn_vec_kernel<<<(NN * 32 + 255) / 256, 256>>>(a_src, a_tgt);
    hist_kernel<<<(EE + 255) / 256, 256>>>(ei);
    scan_kernel<<<1, 1024>>>();
    permute_kernel<<<(EE + 255) / 256, 256>>>(ei, ew);
    gather_kernel<<<(NN * 32 + 255) / 256, 256>>>(out);
}

// round 13
// speedup vs baseline: 1.4856x; 1.4856x over previous
#include <cuda_runtime.h>

#define NN   100000
#define EE   3200000
#define IND  128
#define OUTD 64

// Scratch (device globals — no allocation allowed)
__device__ float g_h[NN * OUTD];      // 25.6 MB
__device__ float g_hs[NN];
__device__ float g_ht[NN];
__device__ int   g_deg[NN];
__device__ int   g_cur[NN];           // running cursor, pre-seeded = g_off
__device__ int   g_off[NN + 1];
__device__ int2  g_sp[EE];            // {src, bitcast(p)} permuted by target
__device__ int   g_is64;              // 1 if edge_index is int64, 0 if int32

// ---------------------------------------------------------------------------
// Detect edge_index dtype (warp-parallel, no serial chain): int64 values
// < 2^31 have zero odd 32-bit words; 128 random int32 ids all-zero: P~0.
// ---------------------------------------------------------------------------
__global__ void detect_kernel(const int* __restrict__ ei_raw) {
    int lane = threadIdx.x;
    int nz = 0;
    #pragma unroll
    for (int i = 0; i < 4; ++i) nz |= __ldg(ei_raw + 2 * (lane * 4 + i) + 1);
    unsigned m = __ballot_sync(0xFFFFFFFFu, nz != 0);
    if (lane == 0) g_is64 = (m == 0);
}

// Decode index and clamp into [0, NN) — diagnostic guard, cost hidden
// under the index LDG latency.
__device__ __forceinline__ int clampi(int v) {
    return min(max(v, 0), NN - 1);
}

// ---------------------------------------------------------------------------
// Zero the degree histogram
// ---------------------------------------------------------------------------
__global__ void zero_kernel() {
    int i = blockIdx.x * blockDim.x + threadIdx.x;
    if (i < NN) g_deg[i] = 0;
}

// ---------------------------------------------------------------------------
// h = x @ W  fused with  hs = h@a_src, ht = h@a_tgt.
// Block 256: 16 threads per row (4 cols each), 16 rows per tile, 4 tiles.
// ---------------------------------------------------------------------------
__global__ __launch_bounds__(256) void gemm_attn_kernel(const float* __restrict__ x,
                                                        const float* __restrict__ W,
                                                        const float* __restrict__ a_src,
                                                        const float* __restrict__ a_tgt) {
    __shared__ float4 Ws4[IND * 16];   // 32 KB: Ws4[k*16+cg] = W[k][4cg..4cg+3]
    __shared__ float  xs[16 * IND];    // 8 KB
    __shared__ float  as_s[OUTD], at_s[OUTD];

    const int tid = threadIdx.x;
    for (int i = tid; i < IND * 16; i += 256)
        Ws4[i] = reinterpret_cast<const float4*>(W)[i];
    if (tid < OUTD) { as_s[tid] = a_src[tid]; at_s[tid] = a_tgt[tid]; }

    const int r  = tid >> 4;           // 0..15 row-in-tile
    const int cg = tid & 15;           // 0..15 col-group (4 cols)
    const int rowBase = blockIdx.x * 64;

    for (int it = 0; it < 4; ++it) {
        const int r0 = rowBase + it * 16;
        __syncthreads();
        // stage 16 rows of x: 512 float4, 2 per thread
        for (int i = tid; i < 16 * IND / 4; i += 256) {
            int rr = r0 + (i * 4) / IND;
            float4 v = make_float4(0.f, 0.f, 0.f, 0.f);
            if (rr < NN)
                v = reinterpret_cast<const float4*>(x)[(size_t)r0 * (IND / 4) + i];
            reinterpret_cast<float4*>(xs)[i] = v;
        }
        __syncthreads();

        float4 acc = make_float4(0.f, 0.f, 0.f, 0.f);
        const float* xr = xs + r * IND;
        #pragma unroll 8
        for (int k = 0; k < IND; ++k) {
            float  xv = xr[k];
            float4 wv = Ws4[k * 16 + cg];
            acc.x += xv * wv.x;
            acc.y += xv * wv.y;
            acc.z += xv * wv.z;
            acc.w += xv * wv.w;
        }
        const int row = r0 + r;
        if (row < NN)
            reinterpret_cast<float4*>(g_h)[(size_t)row * 16 + cg] = acc;

        // fused attention logits: reduce over the 16 lanes holding this row
        float ps = acc.x * as_s[cg * 4] + acc.y * as_s[cg * 4 + 1]
                 + acc.z * as_s[cg * 4 + 2] + acc.w * as_s[cg * 4 + 3];
        float pt = acc.x * at_s[cg * 4] + acc.y * at_s[cg * 4 + 1]
                 + acc.z * at_s[cg * 4 + 2] + acc.w * at_s[cg * 4 + 3];
        #pragma unroll
        for (int o = 8; o; o >>= 1) {
            ps += __shfl_xor_sync(0xFFFFFFFFu, ps, o, 16);
            pt += __shfl_xor_sync(0xFFFFFFFFu, pt, o, 16);
        }
        if (cg == 0 && row < NN) { g_hs[row] = ps; g_ht[row] = pt; }
    }
}

// ---------------------------------------------------------------------------
// Degree histogram over targets — 4 edges per thread, int4 index loads
// ---------------------------------------------------------------------------
__global__ __launch_bounds__(256) void hist_kernel(const void* __restrict__ ei) {
    int q = blockIdx.x * blockDim.x + threadIdx.x;   // quad index
    if (q >= EE / 4) return;
    if (g_is64) {
        const long long* p = (const long long*)ei + EE + q * 4;
        #pragma unroll
        for (int i = 0; i < 4; ++i) atomicAdd(&g_deg[clampi((int)p[i])], 1);
    } else {
        int4 t4 = __ldg((const int4*)((const int*)ei + EE) + q);
        atomicAdd(&g_deg[clampi(t4.x)], 1);
        atomicAdd(&g_deg[clampi(t4.y)], 1);
        atomicAdd(&g_deg[clampi(t4.z)], 1);
        atomicAdd(&g_deg[clampi(t4.w)], 1);
    }
}

// ---------------------------------------------------------------------------
// Exclusive scan of g_deg -> g_off, also seeding g_cur = g_off
// ---------------------------------------------------------------------------
__global__ __launch_bounds__(1024) void scan_kernel() {
    __shared__ int partial[1024];
    const int CH  = (NN + 1023) / 1024;        // 98
    const int tid = threadIdx.x;
    const int begin = tid * CH;
    const int end   = min(begin + CH, NN);

    int sum = 0;
    for (int i = begin; i < end; ++i) sum += g_deg[i];
    partial[tid] = sum;
    __syncthreads();

    for (int off = 1; off < 1024; off <<= 1) {
        int v = (tid >= off) ? partial[tid - off] : 0;
        __syncthreads();
        partial[tid] += v;
        __syncthreads();
    }

    int run = (tid == 0) ? 0 : partial[tid - 1];
    for (int i = begin; i < end; ++i) {
        g_off[i] = run;
        g_cur[i] = run;
        run += g_deg[i];
    }
    if (tid == 1023) g_off[NN] = run;          // == EE
}

// ---------------------------------------------------------------------------
// Permute edges into target-sorted buckets — 4 edges per thread
// ---------------------------------------------------------------------------
__global__ __launch_bounds__(256) void permute_kernel(const void* __restrict__ ei,
                                                      const float* __restrict__ w) {
    int q = blockIdx.x * blockDim.x + threadIdx.x;
    if (q >= EE / 4) return;

    int s[4], t[4];
    if (g_is64) {
        const long long* ps = (const long long*)ei + q * 4;
        const long long* pt = (const long long*)ei + EE + q * 4;
        #pragma unroll
        for (int i = 0; i < 4; ++i) { s[i] = clampi((int)ps[i]); t[i] = clampi((int)pt[i]); }
    } else {
        int4 s4 = __ldg((const int4*)ei + q);
        int4 t4 = __ldg((const int4*)((const int*)ei + EE) + q);
        s[0] = clampi(s4.x); s[1] = clampi(s4.y); s[2] = clampi(s4.z); s[3] = clampi(s4.w);
        t[0] = clampi(t4.x); t[1] = clampi(t4.y); t[2] = clampi(t4.z); t[3] = clampi(t4.w);
    }
    float4 w4 = __ldg((const float4*)w + q);
    float ww[4] = {w4.x, w4.y, w4.z, w4.w};

    #pragma unroll
    for (int i = 0; i < 4; ++i) {
        float v = g_hs[s[i]] + g_ht[t[i]];
        v = v > 0.f ? v : 0.2f * v;
        v *= ww[i];
        float p = __expf(v);
        int pos = atomicAdd(&g_cur[t[i]], 1);
        g_sp[pos] = make_int2(s[i], __float_as_int(p));
    }
}

// ---------------------------------------------------------------------------
// Gather: one warp per target node, single fused pass.
//   out[t] = inv * sum_e p_e * h[src_e]
// Descriptors: coalesced lane load -> smem -> broadcast LDS.64 per edge.
// h rows: one LDG.64 (float2) per lane per edge.
// ---------------------------------------------------------------------------
__global__ __launch_bounds__(256) void gather_kernel(float* __restrict__ out) {
    __shared__ int2 ds[8][32];
    const int wIdx = threadIdx.x >> 5;
    const int lane = threadIdx.x & 31;
    const int t    = blockIdx.x * 8 + wIdx;
    if (t >= NN) return;

    const int base = g_off[t];
    const int end  = g_off[t + 1];

    float psum = 0.f;
    float2 a = make_float2(0.f, 0.f);

    for (int cbase = base; cbase < end; cbase += 32) {
        const int n = min(32, end - cbase);
        int2 my = make_int2(0, 0);                       // p bitcast 0.0f
        if (lane < n) my = __ldg(&g_sp[cbase + lane]);
        psum += __int_as_float(my.y);
        ds[wIdx][lane] = my;
        __syncwarp();
        if (n == 32) {
            #pragma unroll 8
            for (int k = 0; k < 32; ++k) {
                int2 d = ds[wIdx][k];
                float p = __int_as_float(d.y);
                float2 hv = __ldg((const float2*)(g_h + (size_t)d.x * OUTD) + lane);
                a.x += p * hv.x;
                a.y += p * hv.y;
            }
        } else {
            for (int k = 0; k < n; ++k) {
                int2 d = ds[wIdx][k];
                float p = __int_as_float(d.y);
                float2 hv = __ldg((const float2*)(g_h + (size_t)d.x * OUTD) + lane);
                a.x += p * hv.x;
                a.y += p * hv.y;
            }
        }
        __syncwarp();
    }

    #pragma unroll
    for (int o = 16; o; o >>= 1)
        psum += __shfl_xor_sync(0xFFFFFFFFu, psum, o);
    const float inv = 1.0f / (psum + 1e-10f);

    reinterpret_cast<float2*>(out)[(size_t)t * 32 + lane] =
        make_float2(a.x * inv, a.y * inv);
}

// ---------------------------------------------------------------------------
extern "C" void kernel_launch(void* const* d_in, const int* in_sizes, int n_in,
                              void* d_out, int out_size) {
    const float* x      = (const float*)d_in[0];
    const void*  ei     = d_in[1];
    const float* ew     = (const float*)d_in[2];
    const float* W      = (const float*)d_in[3];
    const float* a_src  = (const float*)d_in[4];
    const float* a_tgt  = (const float*)d_in[5];
    float*       out    = (float*)d_out;

    detect_kernel<<<1, 32>>>((const int*)ei);
    zero_kernel<<<(NN + 255) / 256, 256>>>();
    gemm_attn_kernel<<<(NN + 63) / 64, 256>>>(x, W, a_src, a_tgt);
    hist_kernel<<<(EE / 4 + 255) / 256, 256>>>(ei);
    scan_kernel<<<1, 1024>>>();
    permute_kernel<<<(EE / 4 + 255) / 256, 256>>>(ei, ew);
    gather_kernel<<<(NN + 7) / 8, 256>>>(out);
}

// round 16
// speedup vs baseline: 1.7374x; 1.1695x over previous
#include <cuda_runtime.h>

#define NN   100000
#define EE   3200000
#define IND  128
#define OUTD 64

// Scratch (device globals — no allocation allowed)
__device__ float g_h[NN * OUTD];      // 25.6 MB
__device__ float g_hs[NN];
__device__ float g_ht[NN];
__device__ int   g_deg[NN];
__device__ int   g_off[NN + 1];
__device__ int   g_rank[EE];          // within-bucket rank of each edge
__device__ int2  g_sp[EE];            // {src, bitcast(p)} permuted by target
__device__ int   g_is64;              // 1 if edge_index is int64, 0 if int32

// ---------------------------------------------------------------------------
// Detect edge_index dtype (warp-parallel): int64 values < 2^31 have zero odd
// 32-bit words; 128 random int32 ids all-zero: P~0.
// ---------------------------------------------------------------------------
__global__ void detect_kernel(const int* __restrict__ ei_raw) {
    int lane = threadIdx.x;
    int nz = 0;
    #pragma unroll
    for (int i = 0; i < 4; ++i) nz |= __ldg(ei_raw + 2 * (lane * 4 + i) + 1);
    unsigned m = __ballot_sync(0xFFFFFFFFu, nz != 0);
    if (lane == 0) g_is64 = (m == 0);
}

__device__ __forceinline__ int clampi(int v) {
    return min(max(v, 0), NN - 1);
}

// ---------------------------------------------------------------------------
// Zero the degree histogram
// ---------------------------------------------------------------------------
__global__ void zero_kernel() {
    int i = blockIdx.x * blockDim.x + threadIdx.x;
    if (i < NN) g_deg[i] = 0;
}

// ---------------------------------------------------------------------------
// h = x @ W  fused with  hs = h@a_src, ht = h@a_tgt.
// Block 256: 16 threads per row (4 cols each), 16 rows per tile, 4 tiles.
// ---------------------------------------------------------------------------
__global__ __launch_bounds__(256) void gemm_attn_kernel(const float* __restrict__ x,
                                                        const float* __restrict__ W,
                                                        const float* __restrict__ a_src,
                                                        const float* __restrict__ a_tgt) {
    __shared__ float4 Ws4[IND * 16];   // 32 KB
    __shared__ float  xs[16 * IND];    // 8 KB
    __shared__ float  as_s[OUTD], at_s[OUTD];

    const int tid = threadIdx.x;
    for (int i = tid; i < IND * 16; i += 256)
        Ws4[i] = reinterpret_cast<const float4*>(W)[i];
    if (tid < OUTD) { as_s[tid] = a_src[tid]; at_s[tid] = a_tgt[tid]; }

    const int r  = tid >> 4;           // 0..15 row-in-tile
    const int cg = tid & 15;           // 0..15 col-group (4 cols)
    const int rowBase = blockIdx.x * 64;

    for (int it = 0; it < 4; ++it) {
        const int r0 = rowBase + it * 16;
        __syncthreads();
        for (int i = tid; i < 16 * IND / 4; i += 256) {
            int rr = r0 + (i * 4) / IND;
            float4 v = make_float4(0.f, 0.f, 0.f, 0.f);
            if (rr < NN)
                v = reinterpret_cast<const float4*>(x)[(size_t)r0 * (IND / 4) + i];
            reinterpret_cast<float4*>(xs)[i] = v;
        }
        __syncthreads();

        float4 acc = make_float4(0.f, 0.f, 0.f, 0.f);
        const float* xr = xs + r * IND;
        #pragma unroll 8
        for (int k = 0; k < IND; ++k) {
            float  xv = xr[k];
            float4 wv = Ws4[k * 16 + cg];
            acc.x += xv * wv.x;
            acc.y += xv * wv.y;
            acc.z += xv * wv.z;
            acc.w += xv * wv.w;
        }
        const int row = r0 + r;
        if (row < NN)
            reinterpret_cast<float4*>(g_h)[(size_t)row * 16 + cg] = acc;

        float ps = acc.x * as_s[cg * 4] + acc.y * as_s[cg * 4 + 1]
                 + acc.z * as_s[cg * 4 + 2] + acc.w * as_s[cg * 4 + 3];
        float pt = acc.x * at_s[cg * 4] + acc.y * at_s[cg * 4 + 1]
                 + acc.z * at_s[cg * 4 + 2] + acc.w * at_s[cg * 4 + 3];
        #pragma unroll
        for (int o = 8; o; o >>= 1) {
            ps += __shfl_xor_sync(0xFFFFFFFFu, ps, o, 16);
            pt += __shfl_xor_sync(0xFFFFFFFFu, pt, o, 16);
        }
        if (cg == 0 && row < NN) { g_hs[row] = ps; g_ht[row] = pt; }
    }
}

// ---------------------------------------------------------------------------
// Degree histogram over targets — also records each edge's within-bucket
// rank (the atomic's return value), so permute needs NO atomics.
// ---------------------------------------------------------------------------
__global__ __launch_bounds__(256) void hist_kernel(const void* __restrict__ ei) {
    int q = blockIdx.x * blockDim.x + threadIdx.x;   // quad index
    if (q >= EE / 4) return;
    int t[4];
    if (g_is64) {
        const long long* p = (const long long*)ei + EE + q * 4;
        #pragma unroll
        for (int i = 0; i < 4; ++i) t[i] = clampi((int)p[i]);
    } else {
        int4 t4 = __ldg((const int4*)((const int*)ei + EE) + q);
        t[0] = clampi(t4.x); t[1] = clampi(t4.y); t[2] = clampi(t4.z); t[3] = clampi(t4.w);
    }
    int4 r4;
    r4.x = atomicAdd(&g_deg[t[0]], 1);
    r4.y = atomicAdd(&g_deg[t[1]], 1);
    r4.z = atomicAdd(&g_deg[t[2]], 1);
    r4.w = atomicAdd(&g_deg[t[3]], 1);
    reinterpret_cast<int4*>(g_rank)[q] = r4;
}

// ---------------------------------------------------------------------------
// Exclusive scan of g_deg -> g_off (single block, 1024 threads, chunked)
// ---------------------------------------------------------------------------
__global__ __launch_bounds__(1024) void scan_kernel() {
    __shared__ int partial[1024];
    const int CH  = (NN + 1023) / 1024;        // 98
    const int tid = threadIdx.x;
    const int begin = tid * CH;
    const int end   = min(begin + CH, NN);

    int sum = 0;
    for (int i = begin; i < end; ++i) sum += g_deg[i];
    partial[tid] = sum;
    __syncthreads();

    for (int off = 1; off < 1024; off <<= 1) {
        int v = (tid >= off) ? partial[tid - off] : 0;
        __syncthreads();
        partial[tid] += v;
        __syncthreads();
    }

    int run = (tid == 0) ? 0 : partial[tid - 1];
    for (int i = begin; i < end; ++i) { g_off[i] = run; run += g_deg[i]; }
    if (tid == 1023) g_off[NN] = run;          // == EE
}

// ---------------------------------------------------------------------------
// Permute edges into target-sorted buckets (atomic-free):
//   g_sp[g_off[t] + rank[e]] = {src, p},  p = exp(lrelu(hs[s]+ht[t])*w)
// ---------------------------------------------------------------------------
__global__ __launch_bounds__(256) void permute_kernel(const void* __restrict__ ei,
                                                      const float* __restrict__ w) {
    int q = blockIdx.x * blockDim.x + threadIdx.x;
    if (q >= EE / 4) return;

    int s[4], t[4];
    if (g_is64) {
        const long long* ps = (const long long*)ei + q * 4;
        const long long* pt = (const long long*)ei + EE + q * 4;
        #pragma unroll
        for (int i = 0; i < 4; ++i) { s[i] = clampi((int)ps[i]); t[i] = clampi((int)pt[i]); }
    } else {
        int4 s4 = __ldg((const int4*)ei + q);
        int4 t4 = __ldg((const int4*)((const int*)ei + EE) + q);
        s[0] = clampi(s4.x); s[1] = clampi(s4.y); s[2] = clampi(s4.z); s[3] = clampi(s4.w);
        t[0] = clampi(t4.x); t[1] = clampi(t4.y); t[2] = clampi(t4.z); t[3] = clampi(t4.w);
    }
    float4 w4 = __ldg((const float4*)w + q);
    float ww[4] = {w4.x, w4.y, w4.z, w4.w};
    int4 r4 = __ldg((const int4*)g_rank + q);
    int rr[4] = {r4.x, r4.y, r4.z, r4.w};

    #pragma unroll
    for (int i = 0; i < 4; ++i) {
        float v = g_hs[s[i]] + g_ht[t[i]];
        v = v > 0.f ? v : 0.2f * v;
        v *= ww[i];
        float p = __expf(v);
        g_sp[g_off[t[i]] + rr[i]] = make_int2(s[i], __float_as_int(p));
    }
}

// ---------------------------------------------------------------------------
// Gather: one warp per target node; TWO edges per iteration.
// Lanes 0-15 process edge A's 64-float row as float4, lanes 16-31 edge B.
// One LDG.128 covers both edges (512B). Cross-half shfl_xor(16) combines.
// ---------------------------------------------------------------------------
__global__ __launch_bounds__(256) void gather_kernel(float* __restrict__ out) {
    __shared__ int2 ds[8][32];
    const int wIdx = threadIdx.x >> 5;
    const int lane = threadIdx.x & 31;
    const int half = lane >> 4;        // 0: edge A, 1: edge B
    const int le   = lane & 15;        // float4 slot within the row
    const int t    = blockIdx.x * 8 + wIdx;
    if (t >= NN) return;

    const int base = g_off[t];
    const int end  = g_off[t + 1];

    float  psum = 0.f;
    float4 a = make_float4(0.f, 0.f, 0.f, 0.f);

    for (int cbase = base; cbase < end; cbase += 32) {
        const int n = min(32, end - cbase);
        int2 my = make_int2(0, 0);                       // p bitcast 0.0f
        if (lane < n) my = __ldg(&g_sp[cbase + lane]);
        psum += __int_as_float(my.y);
        ds[wIdx][lane] = my;
        __syncwarp();

        int k = 0;
        #pragma unroll 4
        for (; k + 2 <= n; k += 2) {
            int2 d  = ds[wIdx][k + half];
            float p = __int_as_float(d.y);
            float4 hv = __ldg(reinterpret_cast<const float4*>(g_h + (size_t)d.x * OUTD) + le);
            a.x += p * hv.x;
            a.y += p * hv.y;
            a.z += p * hv.z;
            a.w += p * hv.w;
        }
        if (k < n) {                                     // odd tail
            int2 d  = ds[wIdx][k];
            float p = half ? 0.f : __int_as_float(d.y);
            float4 hv = __ldg(reinterpret_cast<const float4*>(g_h + (size_t)d.x * OUTD) + le);
            a.x += p * hv.x;
            a.y += p * hv.y;
            a.z += p * hv.z;
            a.w += p * hv.w;
        }
        __syncwarp();
    }

    // combine the two halves (edge-A accumulator + edge-B accumulator)
    a.x += __shfl_xor_sync(0xFFFFFFFFu, a.x, 16);
    a.y += __shfl_xor_sync(0xFFFFFFFFu, a.y, 16);
    a.z += __shfl_xor_sync(0xFFFFFFFFu, a.z, 16);
    a.w += __shfl_xor_sync(0xFFFFFFFFu, a.w, 16);

    #pragma unroll
    for (int o = 16; o; o >>= 1)
        psum += __shfl_xor_sync(0xFFFFFFFFu, psum, o);
    const float inv = 1.0f / (psum + 1e-10f);

    if (half == 0)
        reinterpret_cast<float4*>(out)[(size_t)t * 16 + le] =
            make_float4(a.x * inv, a.y * inv, a.z * inv, a.w * inv);
}

// ---------------------------------------------------------------------------
extern "C" void kernel_launch(void* const* d_in, const int* in_sizes, int n_in,
                              void* d_out, int out_size) {
    const float* x      = (const float*)d_in[0];
    const void*  ei     = d_in[1];
    const float* ew     = (const float*)d_in[2];
    const float* W      = (const float*)d_in[3];
    const float* a_src  = (const float*)d_in[4];
    const float* a_tgt  = (const float*)d_in[5];
    float*       out    = (float*)d_out;

    detect_kernel<<<1, 32>>>((const int*)ei);
    zero_kernel<<<(NN + 255) / 256, 256>>>();
    gemm_attn_kernel<<<(NN + 63) / 64, 256>>>(x, W, a_src, a_tgt);
    hist_kernel<<<(EE / 4 + 255) / 256, 256>>>(ei);
    scan_kernel<<<1, 1024>>>();
    permute_kernel<<<(EE / 4 + 255) / 256, 256>>>(ei, ew);
    gather_kernel<<<(NN + 7) / 8, 256>>>(out);
}